// round 13
// baseline (speedup 1.0000x reference)
#include <cuda_runtime.h>
#include <cuda_fp16.h>
#include <stdint.h>
#include <math.h>

#define B_ 4
#define L_ 1024
#define H_ 8
#define D_ 64
#define BH_ 32
#define INV_TEMP 0.125f
#define KC 128

typedef unsigned int u32;

__device__ __align__(16) __half g_qh[BH_ * L_ * D_];
__device__ __align__(16) __half g_kh[BH_ * L_ * D_];
__device__ __align__(16) __half g_vh[BH_ * L_ * D_];

__device__ __forceinline__ void ldsm4(u32 addr, u32* r) {
    asm volatile("ldmatrix.sync.aligned.m8n8.x4.shared.b16 {%0,%1,%2,%3}, [%4];"
                 : "=r"(r[0]), "=r"(r[1]), "=r"(r[2]), "=r"(r[3]) : "r"(addr));
}
__device__ __forceinline__ void ldsm4t(u32 addr, u32* r) {
    asm volatile("ldmatrix.sync.aligned.m8n8.x4.trans.shared.b16 {%0,%1,%2,%3}, [%4];"
                 : "=r"(r[0]), "=r"(r[1]), "=r"(r[2]), "=r"(r[3]) : "r"(addr));
}
__device__ __forceinline__ void hmma(float* c, const u32* a, u32 b0, u32 b1) {
    asm volatile(
        "mma.sync.aligned.m16n8k16.row.col.f32.f16.f16.f32 "
        "{%0,%1,%2,%3}, {%4,%5,%6,%7}, {%8,%9}, {%0,%1,%2,%3};"
        : "+f"(c[0]), "+f"(c[1]), "+f"(c[2]), "+f"(c[3])
        : "r"(a[0]), "r"(a[1]), "r"(a[2]), "r"(a[3]), "r"(b0), "r"(b1));
}
__device__ __forceinline__ void cpa16(u32 dst, const void* src) {
    asm volatile("cp.async.cg.shared.global [%0], [%1], 16;" :: "r"(dst), "l"(src));
}
#define CPA_COMMIT() asm volatile("cp.async.commit_group;")
#define CPA_WAIT(n)  asm volatile("cp.async.wait_group " #n ";")

__device__ __forceinline__ u32 pack_h2(float a, float b) {
    half2 h = __floats2half2_rn(a, b);
    return *(u32*)&h;
}

// ---- prep: L2-normalize q,k (fp16); copy v (fp16); [bh][l][d] ----
__global__ void prep_kernel(const float* __restrict__ q,
                            const float* __restrict__ k,
                            const float* __restrict__ v) {
    const int gw = (blockIdx.x * blockDim.x + threadIdx.x) >> 5;
    const int lane = threadIdx.x & 31;
    const int r = gw * 2 + (lane >> 4);
    const int c4 = lane & 15;
    const int b = r / (L_ * H_);
    const int rem = r % (L_ * H_);
    const int l = rem / H_;
    const int h = rem % H_;
    const long src = (((long)b * L_ + l) * H_ + h) * D_ + c4 * 4;
    const long dst = (((long)b * H_ + h) * L_ + l) * D_ + c4 * 4;

    float4 qv = *(const float4*)(q + src);
    float ss = qv.x * qv.x + qv.y * qv.y + qv.z * qv.z + qv.w * qv.w;
#pragma unroll
    for (int o = 1; o < 16; o <<= 1) ss += __shfl_xor_sync(0xffffffffu, ss, o);
    float sc = 1.0f / fmaxf(sqrtf(ss), 1e-8f);
    uint2 pk;
    pk.x = pack_h2(qv.x * sc, qv.y * sc);
    pk.y = pack_h2(qv.z * sc, qv.w * sc);
    *(uint2*)(g_qh + dst) = pk;

    float4 kv = *(const float4*)(k + src);
    ss = kv.x * kv.x + kv.y * kv.y + kv.z * kv.z + kv.w * kv.w;
#pragma unroll
    for (int o = 1; o < 16; o <<= 1) ss += __shfl_xor_sync(0xffffffffu, ss, o);
    sc = 1.0f / fmaxf(sqrtf(ss), 1e-8f);
    pk.x = pack_h2(kv.x * sc, kv.y * sc);
    pk.y = pack_h2(kv.z * sc, kv.w * sc);
    *(uint2*)(g_kh + dst) = pk;

    float4 vv = *(const float4*)(v + src);
    pk.x = pack_h2(vv.x, vv.y);
    pk.y = pack_h2(vv.z, vv.w);
    *(uint2*)(g_vh + dst) = pk;
}

// SMEM: sQ @0 (4096B swizzled), sRed @4096 (512B), K/V ring @4608 (3x16384)
//       red (O-reduce) aliases the ring @4608
#define SQ_OFF   0
#define SRED_OFF 4096
#define SKV_OFF  4608
#define RED_OFF  4608
#define RED_STRIDE 68
#define SMEM_BYTES (4608 + 3 * 16384)

// async-load one 128x64 f16 tile, rows PERMUTED within each 32-key window
// (same permutation for K and V keeps QK^T / PV key-consistent)
__device__ __forceinline__ void tile_load_async_perm(u32 dstu, const __half* src, int t) {
#pragma unroll
    for (int i = 0; i < 4; i++) {
        const int idx = t + 256 * i;
        const int row = idx >> 3;
        const int ch = idx & 7;
        const int srow = (row & ~31) | ((row & 4) << 2) | ((row & 2) << 2) |
                         ((row >> 2) & 6) | (row & 1);
        cpa16(dstu + (((srow << 3) | (ch ^ (srow & 7))) << 4), src + idx * 8);
    }
}

__global__ __launch_bounds__(256, 2)
void attn_kernel(float* __restrict__ outp, float* __restrict__ attnp) {
    extern __shared__ char smem[];
    const u32 sbase = (u32)__cvta_generic_to_shared(smem);
    const u32 sQu = sbase + SQ_OFF;
    const u32 skv0 = sbase + SKV_OFF;
    float* sRed = (float*)(smem + SRED_OFF);
    float* red = (float*)(smem + RED_OFF);

    const int t = threadIdx.x;
    const int tx = t & 31;
    const int ty = t >> 5;
    const int wm = ty & 1;            // m16 group
    const int wn = ty >> 1;           // 32-key slice per 128-tile
    const int bh = blockIdx.y;
    const int q0 = blockIdx.x * 32;
    const int g = tx >> 2;
    const int ltg = tx & 3;
    const int lm = tx >> 3;
    const int lr = tx & 7;

    const __half* Qg = g_qh + ((long)bh * L_ + q0) * D_;
    const __half* Kg = g_kh + (long)bh * L_ * D_;
    const __half* Vg = g_vh + (long)bh * L_ * D_;

    u32 ph[64];        // exp(S) fragments, PV-A-ready (permuted keys)
    u32 qf[4][4];      // Q A-frags
    u32 fb[4];

    // Q tile -> SMEM (swizzled)
    {
        const uint4* src = (const uint4*)Qg;
        uint4* dst = (uint4*)(smem + SQ_OFF);
        const int row = t >> 3;
        const int ch = t & 7;
        dst[(row << 3) | (ch ^ (row & 7))] = src[t];
    }

    // prefetch K0, K1 (permuted rows)
    tile_load_async_perm(skv0, Kg, t);
    CPA_COMMIT();
    tile_load_async_perm(skv0 + 16384, Kg + KC * D_, t);
    CPA_COMMIT();

    // ================= phase 1: S fragments in registers =================
#pragma unroll
    for (int kt = 0; kt < 8; kt++) {
        CPA_WAIT(1);
        __syncthreads();
        if (kt == 0) {
#pragma unroll
            for (int kk = 0; kk < 4; kk++) {
                const int arow = 16 * wm + (lm & 1) * 8 + lr;
                const int ach = 2 * kk + (lm >> 1);
                ldsm4(sQu + arow * 128 + ((ach ^ (arow & 7)) << 4), qf[kk]);
            }
        }
        // prefetch tile kt+2 (K for kt<6; V0 at kt==6, V1 at kt==7) — same perm
        {
            const __half* src = (kt < 6) ? (Kg + (size_t)(kt + 2) * KC * D_)
                                         : (Vg + (size_t)(kt - 6) * KC * D_);
            tile_load_async_perm(skv0 + ((kt + 2) % 3) * 16384, src, t);
            CPA_COMMIT();
        }

        const u32 sKVu = skv0 + (kt % 3) * 16384;
        float c[4][4];
#pragma unroll
        for (int nt = 0; nt < 4; nt++) {
            c[nt][0] = 0.0f; c[nt][1] = 0.0f; c[nt][2] = 0.0f; c[nt][3] = 0.0f;
        }
#pragma unroll
        for (int kk = 0; kk < 4; kk++) {
#pragma unroll
            for (int p = 0; p < 2; p++) {
                const int brow = wn * 32 + p * 16 + (lm >> 1) * 8 + lr;
                const int bch = 2 * kk + (lm & 1);
                ldsm4(sKVu + brow * 128 + ((bch ^ (brow & 7)) << 4), fb);
                hmma(c[2 * p], qf[kk], fb[0], fb[1]);
                hmma(c[2 * p + 1], qf[kk], fb[2], fb[3]);
            }
        }
#pragma unroll
        for (int pair = 0; pair < 2; pair++) {
            ph[kt * 8 + pair * 4 + 0] = pack_h2(c[2 * pair][0] * INV_TEMP, c[2 * pair][1] * INV_TEMP);
            ph[kt * 8 + pair * 4 + 1] = pack_h2(c[2 * pair][2] * INV_TEMP, c[2 * pair][3] * INV_TEMP);
            ph[kt * 8 + pair * 4 + 2] = pack_h2(c[2 * pair + 1][0] * INV_TEMP, c[2 * pair + 1][1] * INV_TEMP);
            ph[kt * 8 + pair * 4 + 3] = pack_h2(c[2 * pair + 1][2] * INV_TEMP, c[2 * pair + 1][3] * INV_TEMP);
        }
    }

    // ================= softmax sums (no max shift; |logit| <= 0.125) ===============
    float slo = 0.0f, shi = 0.0f;
#pragma unroll
    for (int i = 0; i < 64; i++) {
        float2 f = __half22float2(*(half2*)&ph[i]);
        float e0 = __expf(f.x);
        float e1 = __expf(f.y);
        if ((i & 1) == 0) slo += e0 + e1; else shi += e0 + e1;
        ph[i] = pack_h2(e0, e1);           // keep UNNORMALIZED exp
    }
    slo += __shfl_xor_sync(0xffffffffu, slo, 1);
    slo += __shfl_xor_sync(0xffffffffu, slo, 2);
    shi += __shfl_xor_sync(0xffffffffu, shi, 1);
    shi += __shfl_xor_sync(0xffffffffu, shi, 2);
    if (ltg == 0) {
        sRed[(16 * wm + g) * 4 + wn] = slo;
        sRed[(16 * wm + g + 8) * 4 + wn] = shi;
    }
    __syncthreads();
    float inv_lo, inv_hi;
    {
        const int rlo = (16 * wm + g) * 4;
        const int rhi = (16 * wm + g + 8) * 4;
        inv_lo = 1.0f / (sRed[rlo] + sRed[rlo + 1] + sRed[rlo + 2] + sRed[rlo + 3]);
        inv_hi = 1.0f / (sRed[rhi] + sRed[rhi + 1] + sRed[rhi + 2] + sRed[rhi + 3]);
    }

    // ---- attn write: 8 contiguous cols per (row, kt) -> 2x STG.128 ----
    {
        float* rowp = attnp + ((long)bh * L_ + q0 + 16 * wm + g) * L_ + wn * 32 + 8 * ltg;
#pragma unroll
        for (int kt = 0; kt < 8; kt++) {
#pragma unroll
            for (int r = 0; r < 2; r++) {
                const float inv = r ? inv_hi : inv_lo;
                float2 e0 = __half22float2(*(half2*)&ph[kt * 8 + 0 + r]);
                float2 e1 = __half22float2(*(half2*)&ph[kt * 8 + 2 + r]);
                float2 e2 = __half22float2(*(half2*)&ph[kt * 8 + 4 + r]);
                float2 e3 = __half22float2(*(half2*)&ph[kt * 8 + 6 + r]);
                float* p = rowp + (long)r * 8 * L_ + kt * 128;
                __stcs((float4*)p,       make_float4(e0.x * inv, e0.y * inv, e1.x * inv, e1.y * inv));
                __stcs((float4*)(p + 4), make_float4(e2.x * inv, e2.y * inv, e3.x * inv, e3.y * inv));
            }
        }
    }

    // ================= phase 3: O partials = exp(S) @ V (smem ring + ldsm4t) ======
    float oc[8][4];
#pragma unroll
    for (int d = 0; d < 8; d++) {
        oc[d][0] = 0.0f; oc[d][1] = 0.0f; oc[d][2] = 0.0f; oc[d][3] = 0.0f;
    }

#pragma unroll
    for (int vc = 0; vc < 8; vc++) {
        if (vc == 7) { CPA_WAIT(0); } else { CPA_WAIT(1); }
        __syncthreads();
        if (vc < 6) {
            tile_load_async_perm(skv0 + ((vc + 4) % 3) * 16384,
                                 Vg + (size_t)(vc + 2) * KC * D_, t);
            CPA_COMMIT();
        }
        const u32 sVu = skv0 + ((vc + 2) % 3) * 16384;
#pragma unroll
        for (int pair = 0; pair < 2; pair++) {
            const u32* aP = &ph[vc * 8 + pair * 4];
            const int srow = wn * 32 + pair * 16 + (lm & 1) * 8 + lr;
#pragma unroll
            for (int db = 0; db < 4; db++) {
                const int sch = 2 * db + (lm >> 1);
                ldsm4t(sVu + srow * 128 + ((sch ^ (srow & 7)) << 4), fb);
                hmma(oc[2 * db],     aP, fb[0], fb[1]);
                hmma(oc[2 * db + 1], aP, fb[2], fb[3]);
            }
        }
    }

    // ================= O reduction across 4 wn (scaled by 1/Z) ====================
    __syncthreads();   // ring reads done before aliasing red
    {
        const int buf = (wm * 4 + wn) * 16;
#pragma unroll
        for (int db = 0; db < 8; db++) {
            const int ncol = 8 * db + 2 * ltg;
            *(float2*)&red[(buf + g) * RED_STRIDE + ncol] =
                make_float2(oc[db][0] * inv_lo, oc[db][1] * inv_lo);
            *(float2*)&red[(buf + g + 8) * RED_STRIDE + ncol] =
                make_float2(oc[db][2] * inv_hi, oc[db][3] * inv_hi);
        }
    }
    __syncthreads();
    {
        const int r = t >> 3;
        const int seg = t & 7;
        float acc[8];
#pragma unroll
        for (int j = 0; j < 8; j++) acc[j] = 0.0f;
#pragma unroll
        for (int w = 0; w < 4; w++) {
            const float* src = &red[(((r >> 4) * 4 + w) * 16 + (r & 15)) * RED_STRIDE + seg * 8];
#pragma unroll
            for (int j = 0; j < 8; j++) acc[j] += src[j];
        }
        float* dst = outp + ((long)bh * L_ + q0 + r) * D_ + seg * 8;
        *(float4*)dst       = make_float4(acc[0], acc[1], acc[2], acc[3]);
        *(float4*)(dst + 4) = make_float4(acc[4], acc[5], acc[6], acc[7]);
    }
}

extern "C" void kernel_launch(void* const* d_in, const int* in_sizes, int n_in,
                              void* d_out, int out_size) {
    const float* q = (const float*)d_in[0];
    const float* k = (const float*)d_in[1];
    const float* v = (const float*)d_in[2];
    float* outp  = (float*)d_out;
    float* attnp = outp + (long)BH_ * L_ * D_;

    prep_kernel<<<2048, 256>>>(q, k, v);

    cudaFuncSetAttribute(attn_kernel, cudaFuncAttributeMaxDynamicSharedMemorySize,
                         SMEM_BYTES);
    dim3 grid(L_ / 32, BH_);
    attn_kernel<<<grid, 256, SMEM_BYTES>>>(outp, attnp);
}

// round 14
// speedup vs baseline: 1.5219x; 1.5219x over previous
#include <cuda_runtime.h>
#include <cuda_fp16.h>
#include <stdint.h>
#include <math.h>

#define B_ 4
#define L_ 1024
#define H_ 8
#define D_ 64
#define BH_ 32
#define INV_TEMP 0.125f
#define KC 128

typedef unsigned int u32;

__device__ __align__(16) __half g_qh[BH_ * L_ * D_];
__device__ __align__(16) __half g_kh[BH_ * L_ * D_];
__device__ __align__(16) __half g_vh[BH_ * L_ * D_];

__device__ __forceinline__ void ldsm4(u32 addr, u32* r) {
    asm volatile("ldmatrix.sync.aligned.m8n8.x4.shared.b16 {%0,%1,%2,%3}, [%4];"
                 : "=r"(r[0]), "=r"(r[1]), "=r"(r[2]), "=r"(r[3]) : "r"(addr));
}
__device__ __forceinline__ void ldsm4t(u32 addr, u32* r) {
    asm volatile("ldmatrix.sync.aligned.m8n8.x4.trans.shared.b16 {%0,%1,%2,%3}, [%4];"
                 : "=r"(r[0]), "=r"(r[1]), "=r"(r[2]), "=r"(r[3]) : "r"(addr));
}
__device__ __forceinline__ void hmma(float* c, const u32* a, u32 b0, u32 b1) {
    asm volatile(
        "mma.sync.aligned.m16n8k16.row.col.f32.f16.f16.f32 "
        "{%0,%1,%2,%3}, {%4,%5,%6,%7}, {%8,%9}, {%0,%1,%2,%3};"
        : "+f"(c[0]), "+f"(c[1]), "+f"(c[2]), "+f"(c[3])
        : "r"(a[0]), "r"(a[1]), "r"(a[2]), "r"(a[3]), "r"(b0), "r"(b1));
}
__device__ __forceinline__ void cpa16(u32 dst, const void* src) {
    asm volatile("cp.async.cg.shared.global [%0], [%1], 16;" :: "r"(dst), "l"(src));
}
#define CPA_COMMIT() asm volatile("cp.async.commit_group;")
#define CPA_WAIT(n)  asm volatile("cp.async.wait_group " #n ";")

__device__ __forceinline__ u32 pack_h2(float a, float b) {
    half2 h = __floats2half2_rn(a, b);
    return *(u32*)&h;
}

// ---- prep: L2-normalize q,k (fp16); copy v (fp16); [bh][l][d] ----
__global__ void prep_kernel(const float* __restrict__ q,
                            const float* __restrict__ k,
                            const float* __restrict__ v) {
    const int gw = (blockIdx.x * blockDim.x + threadIdx.x) >> 5;
    const int lane = threadIdx.x & 31;
    const int r = gw * 2 + (lane >> 4);
    const int c4 = lane & 15;
    const int b = r / (L_ * H_);
    const int rem = r % (L_ * H_);
    const int l = rem / H_;
    const int h = rem % H_;
    const long src = (((long)b * L_ + l) * H_ + h) * D_ + c4 * 4;
    const long dst = (((long)b * H_ + h) * L_ + l) * D_ + c4 * 4;

    float4 qv = *(const float4*)(q + src);
    float ss = qv.x * qv.x + qv.y * qv.y + qv.z * qv.z + qv.w * qv.w;
#pragma unroll
    for (int o = 1; o < 16; o <<= 1) ss += __shfl_xor_sync(0xffffffffu, ss, o);
    float sc = 1.0f / fmaxf(sqrtf(ss), 1e-8f);
    uint2 pk;
    pk.x = pack_h2(qv.x * sc, qv.y * sc);
    pk.y = pack_h2(qv.z * sc, qv.w * sc);
    *(uint2*)(g_qh + dst) = pk;

    float4 kv = *(const float4*)(k + src);
    ss = kv.x * kv.x + kv.y * kv.y + kv.z * kv.z + kv.w * kv.w;
#pragma unroll
    for (int o = 1; o < 16; o <<= 1) ss += __shfl_xor_sync(0xffffffffu, ss, o);
    sc = 1.0f / fmaxf(sqrtf(ss), 1e-8f);
    pk.x = pack_h2(kv.x * sc, kv.y * sc);
    pk.y = pack_h2(kv.z * sc, kv.w * sc);
    *(uint2*)(g_kh + dst) = pk;

    float4 vv = *(const float4*)(v + src);
    pk.x = pack_h2(vv.x, vv.y);
    pk.y = pack_h2(vv.z, vv.w);
    *(uint2*)(g_vh + dst) = pk;
}

// SMEM: sQ @0 (4096B swizzled), sRed @4096 (512B), K/V ring @4608 (3x16384)
//       red (O-reduce) aliases the ring @4608
#define SQ_OFF   0
#define SRED_OFF 4096
#define SKV_OFF  4608
#define RED_OFF  4608
#define RED_STRIDE 68
#define SMEM_BYTES (4608 + 3 * 16384)

__global__ __launch_bounds__(256, 2)
void attn_kernel(float* __restrict__ outp, float* __restrict__ attnp) {
    extern __shared__ char smem[];
    const u32 sbase = (u32)__cvta_generic_to_shared(smem);
    const u32 sQu = sbase + SQ_OFF;
    const u32 skv0 = sbase + SKV_OFF;
    float* sRed = (float*)(smem + SRED_OFF);
    float* red = (float*)(smem + RED_OFF);

    const int t = threadIdx.x;
    const int tx = t & 31;
    const int ty = t >> 5;
    const int wm = ty & 1;            // m16 group
    const int wn = ty >> 1;           // 32-key slice per 128-tile
    const int bh = blockIdx.y;
    const int q0 = blockIdx.x * 32;
    const int g = tx >> 2;
    const int ltg = tx & 3;
    const int lm = tx >> 3;
    const int lr = tx & 7;

    const __half* Qg = g_qh + ((long)bh * L_ + q0) * D_;
    const __half* Kg = g_kh + (long)bh * L_ * D_;
    const __half* Vg = g_vh + (long)bh * L_ * D_;

    u32 ph[64];        // exp(S) fragments, PV-A-ready (permuted keys)
    u32 qf[4][4];      // Q A-frags
    u32 fb[4];

    // --- precompute permuted+swizzled smem scatter offsets (loop-invariant) ---
    // key bits (c c p h e) -> smem row (p h c c e)
    u32 soff[4];
#pragma unroll
    for (int i = 0; i < 4; i++) {
        const int idx = t + 256 * i;
        const int row = idx >> 3;
        const int ch = idx & 7;
        const int srow = (row & ~31) | ((row & 4) << 2) | ((row & 2) << 2) |
                         ((row >> 2) & 6) | (row & 1);
        soff[i] = ((srow << 3) | (ch ^ (srow & 7))) << 4;
    }
    const __half* gsrc_base0 = (const __half*)0 + (long)t * 8;  // placeholder unused

    // Q tile -> SMEM (swizzled)
    {
        const uint4* src = (const uint4*)Qg;
        uint4* dst = (uint4*)(smem + SQ_OFF);
        const int row = t >> 3;
        const int ch = t & 7;
        dst[(row << 3) | (ch ^ (row & 7))] = src[t];
    }

    // tile loader using hoisted offsets
    const long goff = (long)t * 8;

    // prefetch K0, K1 (permuted rows)
#pragma unroll
    for (int i = 0; i < 4; i++) cpa16(skv0 + soff[i], Kg + goff + 2048 * i);
    CPA_COMMIT();
#pragma unroll
    for (int i = 0; i < 4; i++) cpa16(skv0 + 16384 + soff[i], Kg + KC * D_ + goff + 2048 * i);
    CPA_COMMIT();

    // ================= phase 1: S fragments in registers =================
#pragma unroll
    for (int kt = 0; kt < 8; kt++) {
        CPA_WAIT(1);
        __syncthreads();
        if (kt == 0) {
#pragma unroll
            for (int kk = 0; kk < 4; kk++) {
                const int arow = 16 * wm + (lm & 1) * 8 + lr;
                const int ach = 2 * kk + (lm >> 1);
                ldsm4(sQu + arow * 128 + ((ach ^ (arow & 7)) << 4), qf[kk]);
            }
        }
        // prefetch tile kt+2 (K for kt<6; V0 at kt==6, V1 at kt==7) — same perm
        {
            const __half* src = (kt < 6) ? (Kg + (size_t)(kt + 2) * KC * D_)
                                         : (Vg + (size_t)(kt - 6) * KC * D_);
            const u32 dstu = skv0 + ((kt + 2) % 3) * 16384;
#pragma unroll
            for (int i = 0; i < 4; i++) cpa16(dstu + soff[i], src + goff + 2048 * i);
            CPA_COMMIT();
        }

        const u32 sKVu = skv0 + (kt % 3) * 16384;
        float c[4][4];
#pragma unroll
        for (int nt = 0; nt < 4; nt++) {
            c[nt][0] = 0.0f; c[nt][1] = 0.0f; c[nt][2] = 0.0f; c[nt][3] = 0.0f;
        }
#pragma unroll
        for (int kk = 0; kk < 4; kk++) {
#pragma unroll
            for (int p = 0; p < 2; p++) {
                const int brow = wn * 32 + p * 16 + (lm >> 1) * 8 + lr;
                const int bch = 2 * kk + (lm & 1);
                ldsm4(sKVu + brow * 128 + ((bch ^ (brow & 7)) << 4), fb);
                hmma(c[2 * p], qf[kk], fb[0], fb[1]);
                hmma(c[2 * p + 1], qf[kk], fb[2], fb[3]);
            }
        }
#pragma unroll
        for (int pair = 0; pair < 2; pair++) {
            ph[kt * 8 + pair * 4 + 0] = pack_h2(c[2 * pair][0] * INV_TEMP, c[2 * pair][1] * INV_TEMP);
            ph[kt * 8 + pair * 4 + 1] = pack_h2(c[2 * pair][2] * INV_TEMP, c[2 * pair][3] * INV_TEMP);
            ph[kt * 8 + pair * 4 + 2] = pack_h2(c[2 * pair + 1][0] * INV_TEMP, c[2 * pair + 1][1] * INV_TEMP);
            ph[kt * 8 + pair * 4 + 3] = pack_h2(c[2 * pair + 1][2] * INV_TEMP, c[2 * pair + 1][3] * INV_TEMP);
        }
    }

    // ================= softmax sums (no max shift; |logit| <= 0.125) ===============
    float slo = 0.0f, shi = 0.0f;
#pragma unroll
    for (int i = 0; i < 64; i++) {
        float2 f = __half22float2(*(half2*)&ph[i]);
        float e0 = __expf(f.x);
        float e1 = __expf(f.y);
        if ((i & 1) == 0) slo += e0 + e1; else shi += e0 + e1;
        ph[i] = pack_h2(e0, e1);           // keep UNNORMALIZED exp
    }
    slo += __shfl_xor_sync(0xffffffffu, slo, 1);
    slo += __shfl_xor_sync(0xffffffffu, slo, 2);
    shi += __shfl_xor_sync(0xffffffffu, shi, 1);
    shi += __shfl_xor_sync(0xffffffffu, shi, 2);
    if (ltg == 0) {
        sRed[(16 * wm + g) * 4 + wn] = slo;
        sRed[(16 * wm + g + 8) * 4 + wn] = shi;
    }
    __syncthreads();
    float inv_lo, inv_hi;
    {
        const int rlo = (16 * wm + g) * 4;
        const int rhi = (16 * wm + g + 8) * 4;
        inv_lo = 1.0f / (sRed[rlo] + sRed[rlo + 1] + sRed[rlo + 2] + sRed[rlo + 3]);
        inv_hi = 1.0f / (sRed[rhi] + sRed[rhi + 1] + sRed[rhi + 2] + sRed[rhi + 3]);
    }

    // ---- attn write: 8 contiguous cols per (row, kt) -> 2x STG.128 ----
    {
        float* rowp = attnp + ((long)bh * L_ + q0 + 16 * wm + g) * L_ + wn * 32 + 8 * ltg;
#pragma unroll
        for (int kt = 0; kt < 8; kt++) {
#pragma unroll
            for (int r = 0; r < 2; r++) {
                const float inv = r ? inv_hi : inv_lo;
                float2 e0 = __half22float2(*(half2*)&ph[kt * 8 + 0 + r]);
                float2 e1 = __half22float2(*(half2*)&ph[kt * 8 + 2 + r]);
                float2 e2 = __half22float2(*(half2*)&ph[kt * 8 + 4 + r]);
                float2 e3 = __half22float2(*(half2*)&ph[kt * 8 + 6 + r]);
                float* p = rowp + (long)r * 8 * L_ + kt * 128;
                __stcs((float4*)p,       make_float4(e0.x * inv, e0.y * inv, e1.x * inv, e1.y * inv));
                __stcs((float4*)(p + 4), make_float4(e2.x * inv, e2.y * inv, e3.x * inv, e3.y * inv));
            }
        }
    }

    // ================= phase 3: O partials = exp(S) @ V (smem ring + ldsm4t) ======
    float oc[8][4];
#pragma unroll
    for (int d = 0; d < 8; d++) {
        oc[d][0] = 0.0f; oc[d][1] = 0.0f; oc[d][2] = 0.0f; oc[d][3] = 0.0f;
    }

#pragma unroll
    for (int vc = 0; vc < 8; vc++) {
        if (vc == 7) { CPA_WAIT(0); } else { CPA_WAIT(1); }
        __syncthreads();
        if (vc < 6) {
            const u32 dstu = skv0 + ((vc + 4) % 3) * 16384;
            const __half* src = Vg + (size_t)(vc + 2) * KC * D_;
#pragma unroll
            for (int i = 0; i < 4; i++) cpa16(dstu + soff[i], src + goff + 2048 * i);
            CPA_COMMIT();
        }
        const u32 sVu = skv0 + ((vc + 2) % 3) * 16384;
#pragma unroll
        for (int pair = 0; pair < 2; pair++) {
            const u32* aP = &ph[vc * 8 + pair * 4];
            const int srow = wn * 32 + pair * 16 + (lm & 1) * 8 + lr;
#pragma unroll
            for (int db = 0; db < 4; db++) {
                const int sch = 2 * db + (lm >> 1);
                ldsm4t(sVu + srow * 128 + ((sch ^ (srow & 7)) << 4), fb);
                hmma(oc[2 * db],     aP, fb[0], fb[1]);
                hmma(oc[2 * db + 1], aP, fb[2], fb[3]);
            }
        }
    }

    // ================= O reduction across 4 wn (scaled by 1/Z) ====================
    __syncthreads();   // ring reads done before aliasing red
    {
        const int buf = (wm * 4 + wn) * 16;
#pragma unroll
        for (int db = 0; db < 8; db++) {
            const int ncol = 8 * db + 2 * ltg;
            *(float2*)&red[(buf + g) * RED_STRIDE + ncol] =
                make_float2(oc[db][0] * inv_lo, oc[db][1] * inv_lo);
            *(float2*)&red[(buf + g + 8) * RED_STRIDE + ncol] =
                make_float2(oc[db][2] * inv_hi, oc[db][3] * inv_hi);
        }
    }
    __syncthreads();
    {
        const int r = t >> 3;
        const int seg = t & 7;
        float acc[8];
#pragma unroll
        for (int j = 0; j < 8; j++) acc[j] = 0.0f;
#pragma unroll
        for (int w = 0; w < 4; w++) {
            const float* src = &red[(((r >> 4) * 4 + w) * 16 + (r & 15)) * RED_STRIDE + seg * 8];
#pragma unroll
            for (int j = 0; j < 8; j++) acc[j] += src[j];
        }
        float* dst = outp + ((long)bh * L_ + q0 + r) * D_ + seg * 8;
        *(float4*)dst       = make_float4(acc[0], acc[1], acc[2], acc[3]);
        *(float4*)(dst + 4) = make_float4(acc[4], acc[5], acc[6], acc[7]);
    }
}

extern "C" void kernel_launch(void* const* d_in, const int* in_sizes, int n_in,
                              void* d_out, int out_size) {
    const float* q = (const float*)d_in[0];
    const float* k = (const float*)d_in[1];
    const float* v = (const float*)d_in[2];
    float* outp  = (float*)d_out;
    float* attnp = outp + (long)BH_ * L_ * D_;

    prep_kernel<<<2048, 256>>>(q, k, v);

    cudaFuncSetAttribute(attn_kernel, cudaFuncAttributeMaxDynamicSharedMemorySize,
                         SMEM_BYTES);
    dim3 grid(L_ / 32, BH_);
    attn_kernel<<<grid, 256, SMEM_BYTES>>>(outp, attnp);
}

// round 15
// speedup vs baseline: 1.8162x; 1.1934x over previous
#include <cuda_runtime.h>
#include <cuda_fp16.h>
#include <stdint.h>
#include <math.h>

#define B_ 4
#define L_ 1024
#define H_ 8
#define D_ 64
#define BH_ 32
#define INV_TEMP 0.125f
#define KC 128

typedef unsigned int u32;

__device__ __align__(16) __half g_qh[BH_ * L_ * D_];
__device__ __align__(16) __half g_kh[BH_ * L_ * D_];
__device__ __align__(16) __half g_vh[BH_ * L_ * D_];

__device__ __forceinline__ void ldsm4(u32 addr, u32* r) {
    asm volatile("ldmatrix.sync.aligned.m8n8.x4.shared.b16 {%0,%1,%2,%3}, [%4];"
                 : "=r"(r[0]), "=r"(r[1]), "=r"(r[2]), "=r"(r[3]) : "r"(addr));
}
__device__ __forceinline__ void ldsm4t(u32 addr, u32* r) {
    asm volatile("ldmatrix.sync.aligned.m8n8.x4.trans.shared.b16 {%0,%1,%2,%3}, [%4];"
                 : "=r"(r[0]), "=r"(r[1]), "=r"(r[2]), "=r"(r[3]) : "r"(addr));
}
__device__ __forceinline__ void hmma(float* c, const u32* a, u32 b0, u32 b1) {
    asm volatile(
        "mma.sync.aligned.m16n8k16.row.col.f32.f16.f16.f32 "
        "{%0,%1,%2,%3}, {%4,%5,%6,%7}, {%8,%9}, {%0,%1,%2,%3};"
        : "+f"(c[0]), "+f"(c[1]), "+f"(c[2]), "+f"(c[3])
        : "r"(a[0]), "r"(a[1]), "r"(a[2]), "r"(a[3]), "r"(b0), "r"(b1));
}
__device__ __forceinline__ void cpa16(u32 dst, const void* src) {
    asm volatile("cp.async.cg.shared.global [%0], [%1], 16;" :: "r"(dst), "l"(src));
}
#define CPA_COMMIT() asm volatile("cp.async.commit_group;")
#define CPA_WAIT(n)  asm volatile("cp.async.wait_group " #n ";")

__device__ __forceinline__ u32 pack_h2(float a, float b) {
    half2 h = __floats2half2_rn(a, b);
    return *(u32*)&h;
}

// ---- prep: 2 rows per warp, float4 lanes; L2-normalize q,k; copy v ----
__global__ void prep_kernel(const float* __restrict__ q,
                            const float* __restrict__ k,
                            const float* __restrict__ v) {
    const int gw = (blockIdx.x * blockDim.x + threadIdx.x) >> 5;
    const int lane = threadIdx.x & 31;
    const int r = gw * 2 + (lane >> 4);
    const int c4 = lane & 15;
    const int b = r / (L_ * H_);
    const int rem = r % (L_ * H_);
    const int l = rem / H_;
    const int h = rem % H_;
    const long src = (((long)b * L_ + l) * H_ + h) * D_ + c4 * 4;
    const long dst = (((long)b * H_ + h) * L_ + l) * D_ + c4 * 4;

    float4 qv = *(const float4*)(q + src);
    float ss = qv.x * qv.x + qv.y * qv.y + qv.z * qv.z + qv.w * qv.w;
#pragma unroll
    for (int o = 1; o < 16; o <<= 1) ss += __shfl_xor_sync(0xffffffffu, ss, o);
    float sc = 1.0f / fmaxf(sqrtf(ss), 1e-8f);
    uint2 pk;
    pk.x = pack_h2(qv.x * sc, qv.y * sc);
    pk.y = pack_h2(qv.z * sc, qv.w * sc);
    *(uint2*)(g_qh + dst) = pk;

    float4 kv = *(const float4*)(k + src);
    ss = kv.x * kv.x + kv.y * kv.y + kv.z * kv.z + kv.w * kv.w;
#pragma unroll
    for (int o = 1; o < 16; o <<= 1) ss += __shfl_xor_sync(0xffffffffu, ss, o);
    sc = 1.0f / fmaxf(sqrtf(ss), 1e-8f);
    pk.x = pack_h2(kv.x * sc, kv.y * sc);
    pk.y = pack_h2(kv.z * sc, kv.w * sc);
    *(uint2*)(g_kh + dst) = pk;

    float4 vv = *(const float4*)(v + src);
    pk.x = pack_h2(vv.x, vv.y);
    pk.y = pack_h2(vv.z, vv.w);
    *(uint2*)(g_vh + dst) = pk;
}

// SMEM map:
//   sQ   @0      4096B   (f16 32x64 swizzled)
//   sRed @4096    512B   (f32 [32 rows][4 wn] softmax sums)
//   sKV  @5120   3x16384 (cp.async ring, f16 128x64 swizzled)
//   red  @5120   aliased (f32 O-reduce, 8 bufs x16 rows x68 stride)
#define SQ_OFF   0
#define SRED_OFF 4096
#define SKV_OFF  5120
#define RED_OFF  5120
#define RED_STRIDE 68
#define SMEM_BYTES (5120 + 3 * 16384)

__device__ __forceinline__ void tile_load_async(u32 dstu, const __half* src, int t) {
#pragma unroll
    for (int i = 0; i < 4; i++) {
        const int idx = t + 256 * i;
        const int row = idx >> 3;
        const int ch = idx & 7;
        cpa16(dstu + (((row << 3) | (ch ^ (row & 7))) << 4), src + idx * 8);
    }
}

__global__ __launch_bounds__(256, 2)
void attn_kernel(float* __restrict__ outp, float* __restrict__ attnp) {
    extern __shared__ char smem[];
    const u32 sbase = (u32)__cvta_generic_to_shared(smem);
    const u32 sQu = sbase + SQ_OFF;
    const u32 skv0 = sbase + SKV_OFF;
    float* sRed = (float*)(smem + SRED_OFF);
    float* red = (float*)(smem + RED_OFF);

    const int t = threadIdx.x;
    const int tx = t & 31;
    const int ty = t >> 5;
    const int wm = ty & 1;       // m16 group
    const int wn = ty >> 1;      // warp column 0..3 (n/k slice)
    const int bh = blockIdx.y;
    const int q0 = blockIdx.x * 32;
    const int lg = tx >> 2;
    const int ltg = tx & 3;
    const int lm = tx >> 3;
    const int lr = tx & 7;

    const __half* Qg = g_qh + ((long)bh * L_ + q0) * D_;
    const __half* Kg = g_kh + (long)bh * L_ * D_;
    const __half* Vg = g_vh + (long)bh * L_ * D_;

    u32 ph[64];        // exp(S) fragments: m16 x n256 per warp (half2)
    u32 qf[4][4];      // Q A-fragments, k64
    u32 fb[4];

    // Q tile -> SMEM (swizzled)
    {
        const uint4* src = (const uint4*)Qg;
        uint4* dst = (uint4*)(smem + SQ_OFF);
        const int row = t >> 3;
        const int ch = t & 7;
        dst[(row << 3) | (ch ^ (row & 7))] = src[t];
    }

    // prefetch tiles 0,1 (K0, K1)
    tile_load_async(skv0, Kg, t);
    CPA_COMMIT();
    tile_load_async(skv0 + 16384, Kg + KC * D_, t);
    CPA_COMMIT();

    // ================= phase 1: S fragments in registers =================
#pragma unroll
    for (int kt = 0; kt < 8; kt++) {
        CPA_WAIT(1);
        __syncthreads();
        if (kt == 0) {
            // hoist Q fragments
#pragma unroll
            for (int kk = 0; kk < 4; kk++) {
                const int arow = 16 * wm + (lm & 1) * 8 + lr;
                const int ach = 2 * kk + (lm >> 1);
                ldsm4(sQu + arow * 128 + ((ach ^ (arow & 7)) << 4), qf[kk]);
            }
        }
        // prefetch tile kt+2 (K for kt<6, V0 at kt==6, V1 at kt==7)
        {
            const __half* src = (kt < 6) ? (Kg + (size_t)(kt + 2) * KC * D_)
                                         : (Vg + (size_t)(kt - 6) * KC * D_);
            tile_load_async(skv0 + ((kt + 2) % 3) * 16384, src, t);
            CPA_COMMIT();
        }

        const u32 sKVu = skv0 + (kt % 3) * 16384;
        float c[4][4];
#pragma unroll
        for (int nt = 0; nt < 4; nt++) {
            c[nt][0] = 0.0f; c[nt][1] = 0.0f; c[nt][2] = 0.0f; c[nt][3] = 0.0f;
        }
#pragma unroll
        for (int kk = 0; kk < 4; kk++) {
#pragma unroll
            for (int p = 0; p < 2; p++) {
                const int brow = wn * 32 + p * 16 + (lm >> 1) * 8 + lr;
                const int bch = 2 * kk + (lm & 1);
                ldsm4(sKVu + brow * 128 + ((bch ^ (brow & 7)) << 4), fb);
                hmma(c[2 * p], qf[kk], fb[0], fb[1]);
                hmma(c[2 * p + 1], qf[kk], fb[2], fb[3]);
            }
        }
        // pack scaled logits into A-fragment order
#pragma unroll
        for (int pair = 0; pair < 2; pair++) {
            ph[kt * 8 + pair * 4 + 0] = pack_h2(c[2 * pair][0] * INV_TEMP, c[2 * pair][1] * INV_TEMP);
            ph[kt * 8 + pair * 4 + 1] = pack_h2(c[2 * pair][2] * INV_TEMP, c[2 * pair][3] * INV_TEMP);
            ph[kt * 8 + pair * 4 + 2] = pack_h2(c[2 * pair + 1][0] * INV_TEMP, c[2 * pair + 1][1] * INV_TEMP);
            ph[kt * 8 + pair * 4 + 3] = pack_h2(c[2 * pair + 1][2] * INV_TEMP, c[2 * pair + 1][3] * INV_TEMP);
        }
    }

    // ================= softmax (no max shift; |logit| <= 0.125) =================
    float slo = 0.0f, shi = 0.0f;
#pragma unroll
    for (int i = 0; i < 64; i++) {
        float2 f = __half22float2(*(half2*)&ph[i]);
        float e0 = __expf(f.x);
        float e1 = __expf(f.y);
        if ((i & 1) == 0) slo += e0 + e1; else shi += e0 + e1;
        ph[i] = pack_h2(e0, e1);   // keep UNNORMALIZED exp for PV
    }
    slo += __shfl_xor_sync(0xffffffffu, slo, 1);
    slo += __shfl_xor_sync(0xffffffffu, slo, 2);
    shi += __shfl_xor_sync(0xffffffffu, shi, 1);
    shi += __shfl_xor_sync(0xffffffffu, shi, 2);
    if (ltg == 0) {
        sRed[(16 * wm + lg) * 4 + wn] = slo;
        sRed[(16 * wm + lg + 8) * 4 + wn] = shi;
    }
    __syncthreads();
    float inv_lo, inv_hi;
    {
        const int rlo = 16 * wm + lg;
        inv_lo = 1.0f / (sRed[rlo * 4] + sRed[rlo * 4 + 1] + sRed[rlo * 4 + 2] + sRed[rlo * 4 + 3]);
        inv_hi = 1.0f / (sRed[(rlo + 8) * 4] + sRed[(rlo + 8) * 4 + 1] +
                         sRed[(rlo + 8) * 4 + 2] + sRed[(rlo + 8) * 4 + 3]);
    }

    // normalize at the attn store only (NO repack — ph stays raw exp)
    {
        float* row_lo = attnp + ((long)(bh * L_ + q0 + 16 * wm + lg)) * L_;
        float* row_hi = row_lo + 8 * L_;
#pragma unroll
        for (int i = 0; i < 64; i++) {
            const int col = (i >> 3) * 128 + wn * 32 + ((i >> 2) & 1) * 16 + ((i >> 1) & 1) * 8 + 2 * ltg;
            float2 e = __half22float2(*(half2*)&ph[i]);
            const float inv = (i & 1) ? inv_hi : inv_lo;
            __stcs((float2*)(((i & 1) ? row_hi : row_lo) + col),
                   make_float2(e.x * inv, e.y * inv));
        }
    }

    // ================= phase 3: O partials = exp(S)(k-slice) @ V =================
    float oc[8][4];
#pragma unroll
    for (int d = 0; d < 8; d++) {
        oc[d][0] = 0.0f; oc[d][1] = 0.0f; oc[d][2] = 0.0f; oc[d][3] = 0.0f;
    }

#pragma unroll
    for (int vc = 0; vc < 8; vc++) {
        if (vc == 7) { CPA_WAIT(0); } else { CPA_WAIT(1); }
        __syncthreads();
        if (vc < 6) {
            tile_load_async(skv0 + ((vc + 4) % 3) * 16384, Vg + (size_t)(vc + 2) * KC * D_, t);
            CPA_COMMIT();
        }
        const u32 sVu = skv0 + ((vc + 2) % 3) * 16384;
#pragma unroll
        for (int pair = 0; pair < 2; pair++) {
            const u32* aP = &ph[vc * 8 + pair * 4];
            const int srow = wn * 32 + pair * 16 + (lm & 1) * 8 + lr;
#pragma unroll
            for (int db = 0; db < 4; db++) {
                const int sch = 2 * db + (lm >> 1);
                ldsm4t(sVu + srow * 128 + ((sch ^ (srow & 7)) << 4), fb);
                hmma(oc[2 * db],     aP, fb[0], fb[1]);
                hmma(oc[2 * db + 1], aP, fb[2], fb[3]);
            }
        }
    }

    // ================= O reduction across warp columns (scaled by 1/Z) ============
    __syncthreads();   // all ring reads done before aliasing red over sKV
    {
        const int buf = (wm * 4 + wn) * 16;
#pragma unroll
        for (int t8 = 0; t8 < 8; t8++) {
            *(float2*)&red[(buf + lg) * RED_STRIDE + t8 * 8 + 2 * ltg] =
                make_float2(oc[t8][0] * inv_lo, oc[t8][1] * inv_lo);
            *(float2*)&red[(buf + lg + 8) * RED_STRIDE + t8 * 8 + 2 * ltg] =
                make_float2(oc[t8][2] * inv_hi, oc[t8][3] * inv_hi);
        }
    }
    __syncthreads();
    {
        const int r = t >> 3;         // output row 0..31
        const int seg = t & 7;        // 8-float segment
        float acc[8];
#pragma unroll
        for (int j = 0; j < 8; j++) acc[j] = 0.0f;
#pragma unroll
        for (int w = 0; w < 4; w++) {
            const float* src = &red[(((r >> 4) * 4 + w) * 16 + (r & 15)) * RED_STRIDE + seg * 8];
#pragma unroll
            for (int j = 0; j < 8; j++) acc[j] += src[j];
        }
        float* dst = outp + ((long)(bh * L_ + q0 + r)) * D_ + seg * 8;
        *(float4*)dst = make_float4(acc[0], acc[1], acc[2], acc[3]);
        *(float4*)(dst + 4) = make_float4(acc[4], acc[5], acc[6], acc[7]);
    }
}

extern "C" void kernel_launch(void* const* d_in, const int* in_sizes, int n_in,
                              void* d_out, int out_size) {
    const float* q = (const float*)d_in[0];
    const float* k = (const float*)d_in[1];
    const float* v = (const float*)d_in[2];
    float* outp  = (float*)d_out;
    float* attnp = outp + (long)BH_ * L_ * D_;

    prep_kernel<<<2048, 256>>>(q, k, v);

    cudaFuncSetAttribute(attn_kernel, cudaFuncAttributeMaxDynamicSharedMemorySize,
                         SMEM_BYTES);
    dim3 grid(L_ / 32, BH_);
    attn_kernel<<<grid, 256, SMEM_BYTES>>>(outp, attnp);
}